// round 15
// baseline (speedup 1.0000x reference)
#include <cuda_runtime.h>
#include <cuda_fp16.h>
#include <cstdint>

#define N_NODES 50000
#define N_EDGES 800000
#define DF 256

// ---------------- device scratch ----------------
__device__ int    g_is64;
__device__ int    g_deg[N_NODES];
__device__ int    g_cursor[N_NODES];
__device__ int    g_rowstart[N_NODES + 1];
__device__ int    g_blocksum[64];
__device__ volatile int g_flag[64];
__device__ int    g_nbr[N_EDGES];
__device__ __half g_xb[(size_t)N_NODES * DF];
__device__ __half g_aggh[(size_t)N_NODES * DF];
__device__ __half g_h1b[(size_t)N_NODES * DF];
__device__ __half g_h2b[(size_t)N_NODES * DF];
__device__ __half g_hm[(size_t)N_NODES * DF];
__device__ __half g_w[5][DF * DF];

__device__ __forceinline__ int edge_at(const void* edge, int idx) {
    if (g_is64) return (int)((const long long*)edge)[idx];
    return ((const int*)edge)[idx];
}

// ---------------- helpers ----------------
__device__ __forceinline__ uint32_t s2u(const void* p) {
    uint32_t a;
    asm("{ .reg .u64 t; cvta.to.shared.u64 t, %1; cvt.u32.u64 %0, t; }" : "=r"(a) : "l"(p));
    return a;
}
__device__ __forceinline__ uint32_t pack_f16(float a, float b) {
    __half2 h = __floats2half2_rn(a, b);
    return *reinterpret_cast<uint32_t*>(&h);
}

// ---- fused: weight fp16 convert + x fp16 convert + CSR init + dtype detect ----
// blocks [0,160): 5 weight matrices. [160,160+XBLK): x rows. rest: init.
#define XBLK ((N_NODES * DF / 8 + 255) / 256)
#define IBLK ((N_NODES + 255) / 256)
__global__ void k_convert(const float* __restrict__ w0, const float* __restrict__ w1,
                          const float* __restrict__ w2, const float* __restrict__ w3,
                          const float* __restrict__ w4, const float* __restrict__ x,
                          const void* edge) {
    int b = blockIdx.x;
    if (b >= 160 + XBLK) {
        int i = (b - 160 - XBLK) * blockDim.x + threadIdx.x;
        if (i < N_NODES) { g_deg[i] = 0; g_cursor[i] = 0; }
        if (i < 64) g_flag[i] = 0;
        if (i == 0) {
            const long long* e = (const long long*)edge;
            int ok = 1;
            for (int j = 0; j < 16; j++) {
                long long v = e[j];
                if (v < 0 || v >= (long long)N_NODES) ok = 0;
            }
            g_is64 = ok;
        }
        return;
    }
    const float* src;
    uint4* dst;
    int i;
    if (b < 160) {
        int m = b >> 5;
        i = (b & 31) * blockDim.x + threadIdx.x;
        src = (m == 0) ? w0 : (m == 1) ? w1 : (m == 2) ? w2 : (m == 3) ? w3 : w4;
        dst = (uint4*)g_w[m];
    } else {
        i = (b - 160) * blockDim.x + threadIdx.x;
        if (i >= N_NODES * DF / 8) return;
        src = x;
        dst = (uint4*)g_xb;
    }
    const float4* p = (const float4*)src + (size_t)i * 2;
    float4 v0 = __ldg(p), v1 = __ldg(p + 1);
    uint4 o;
    o.x = pack_f16(v0.x, v0.y); o.y = pack_f16(v0.z, v0.w);
    o.z = pack_f16(v1.x, v1.y); o.w = pack_f16(v1.z, v1.w);
    dst[i] = o;
}

// ---------------- CSR build ----------------
__global__ void k_count(const void* __restrict__ edge) {
    int e = (blockIdx.x * blockDim.x + threadIdx.x) * 2;
    if (e >= N_EDGES) return;
    int d0 = edge_at(edge, N_EDGES + e);
    atomicAdd(&g_deg[d0], 1);
    if (e + 1 < N_EDGES) {
        int d1 = edge_at(edge, N_EDGES + e + 1);
        atomicAdd(&g_deg[d1], 1);
    }
}

// single-kernel scan with decoupled lookback (49 blocks, all co-resident)
__global__ void k_scan() {
    __shared__ int ws[32];
    __shared__ int soff;
    int b = blockIdx.x, t = threadIdx.x, lane = t & 31, w = t >> 5;
    int i = b * 1024 + t;
    int v = (i < N_NODES) ? g_deg[i] : 0;
    int sv = v;
    #pragma unroll
    for (int off = 1; off < 32; off <<= 1) {
        int x = __shfl_up_sync(0xffffffffu, sv, off);
        if (lane >= off) sv += x;
    }
    if (lane == 31) ws[w] = sv;
    __syncthreads();
    if (w == 0) {
        int s = ws[lane];
        #pragma unroll
        for (int off = 1; off < 32; off <<= 1) {
            int x = __shfl_up_sync(0xffffffffu, s, off);
            if (lane >= off) s += x;
        }
        ws[lane] = s;
    }
    __syncthreads();
    int tot = sv + ((w > 0) ? ws[w - 1] : 0);

    // publish this block's total, then wait for predecessors
    if (t == 1023) {
        g_blocksum[b] = tot;
        __threadfence();
        g_flag[b] = 1;
    }
    if (t == 0) {
        int acc = 0;
        for (int j = 0; j < b; j++) {
            while (g_flag[j] == 0) { }
            acc += g_blocksum[j];
        }
        soff = acc;
    }
    __syncthreads();
    int base = soff;
    if (i < N_NODES) g_rowstart[i + 1] = base + tot;
    if (b == 0 && t == 0) g_rowstart[0] = 0;
}

__global__ void k_fill(const void* __restrict__ edge) {
    int e = (blockIdx.x * blockDim.x + threadIdx.x) * 2;
    if (e >= N_EDGES) return;
    {
        int src = edge_at(edge, e);
        int dst = edge_at(edge, N_EDGES + e);
        int p = atomicAdd(&g_cursor[dst], 1);
        g_nbr[g_rowstart[dst] + p] = src;
    }
    if (e + 1 < N_EDGES) {
        int src = edge_at(edge, e + 1);
        int dst = edge_at(edge, N_EDGES + e + 1);
        int p = atomicAdd(&g_cursor[dst], 1);
        g_nbr[g_rowstart[dst] + p] = src;
    }
}

// ---------------- mean aggregation: warp per node, fp16, 8-edge unroll ----------------
__global__ void k_aggregate(const __half* __restrict__ Xb, __half* __restrict__ Oh) {
    int gw = (blockIdx.x * blockDim.x + threadIdx.x) >> 5;
    int lane = threadIdx.x & 31;
    if (gw >= N_NODES) return;
    int s = g_rowstart[gw], e = g_rowstart[gw + 1];
    float acc[8] = {0.f, 0.f, 0.f, 0.f, 0.f, 0.f, 0.f, 0.f};
    int j = s;
    for (; j + 8 <= e; j += 8) {
        uint4 u[8];
        #pragma unroll
        for (int k = 0; k < 8; k++) {
            int sk = g_nbr[j + k];
            u[k] = __ldg((const uint4*)(Xb + (size_t)sk * DF) + lane);
        }
        #pragma unroll
        for (int k = 0; k < 8; k++) {
            const __half2* p = (const __half2*)&u[k];
            #pragma unroll
            for (int i = 0; i < 4; i++) {
                float2 a = __half22float2(p[i]);
                acc[2 * i]     += a.x;
                acc[2 * i + 1] += a.y;
            }
        }
    }
    for (; j + 2 <= e; j += 2) {
        int s0 = g_nbr[j], s1 = g_nbr[j + 1];
        uint4 u0 = __ldg((const uint4*)(Xb + (size_t)s0 * DF) + lane);
        uint4 u1 = __ldg((const uint4*)(Xb + (size_t)s1 * DF) + lane);
        const __half2* p0 = (const __half2*)&u0;
        const __half2* p1 = (const __half2*)&u1;
        #pragma unroll
        for (int i = 0; i < 4; i++) {
            float2 a = __half22float2(p0[i]);
            float2 b = __half22float2(p1[i]);
            acc[2 * i]     += a.x + b.x;
            acc[2 * i + 1] += a.y + b.y;
        }
    }
    if (j < e) {
        int s0 = g_nbr[j];
        uint4 u = __ldg((const uint4*)(Xb + (size_t)s0 * DF) + lane);
        const __half2* up = (const __half2*)&u;
        #pragma unroll
        for (int i = 0; i < 4; i++) {
            float2 a = __half22float2(up[i]);
            acc[2 * i]     += a.x;
            acc[2 * i + 1] += a.y;
        }
    }
    int cnt = e - s;
    float inv = 1.0f / (float)(cnt > 1 ? cnt : 1);
    uint4 o;
    o.x = pack_f16(acc[0] * inv, acc[1] * inv);
    o.y = pack_f16(acc[2] * inv, acc[3] * inv);
    o.z = pack_f16(acc[4] * inv, acc[5] * inv);
    o.w = pack_f16(acc[6] * inv, acc[7] * inv);
    ((uint4*)(Oh + (size_t)gw * DF))[lane] = o;
}

// ======================= pure fp16 mma.sync GEMM =======================
// C = relu?( A1 @ W1^T [+ A2 @ W2^T] + bias ). All operands fp16, fp32 acc.
// CTA 128(M) x 64(N), chunk K=32, double-buffered smem, 2 CTAs/SM.  [R6 structure]

#define S_A 0
#define S_B 10240
#define S_BUF 15360
#define SMEM_GEMM (2 * S_BUF)

__device__ __forceinline__ void ldsm_x4(uint32_t* r, uint32_t addr) {
    asm volatile("ldmatrix.sync.aligned.m8n8.x4.shared.b16 {%0,%1,%2,%3}, [%4];"
                 : "=r"(r[0]), "=r"(r[1]), "=r"(r[2]), "=r"(r[3]) : "r"(addr));
}
__device__ __forceinline__ void mma16816(float* d, const uint32_t* a, uint32_t b0, uint32_t b1) {
    asm volatile(
        "mma.sync.aligned.m16n8k16.row.col.f32.f16.f16.f32 "
        "{%0,%1,%2,%3}, {%4,%5,%6,%7}, {%8,%9}, {%0,%1,%2,%3};"
        : "+f"(d[0]), "+f"(d[1]), "+f"(d[2]), "+f"(d[3])
        : "r"(a[0]), "r"(a[1]), "r"(a[2]), "r"(a[3]), "r"(b0), "r"(b1));
}

__global__ void __launch_bounds__(256, 2) k_gemm_mma(
    const __half* __restrict__ A1, const __half* __restrict__ W1,
    const __half* __restrict__ A2, const __half* __restrict__ W2,
    const float* __restrict__ bias,
    __half* __restrict__ Ch,
    int M, int dual, int relu)
{
    extern __shared__ __align__(16) char smem[];
    uint32_t sb = s2u(smem);
    int tid = threadIdx.x, lane = tid & 31, wid = tid >> 5;
    int bm = blockIdx.x * 128, bn = blockIdx.y * 64;
    int wm = wid & 3, wn = wid >> 2;

    float acc[2][4][4];
    #pragma unroll
    for (int mt = 0; mt < 2; mt++)
        #pragma unroll
        for (int nt = 0; nt < 4; nt++)
            #pragma unroll
            for (int j = 0; j < 4; j++) acc[mt][nt][j] = 0.f;

    int nc = dual ? 16 : 8;
    uint4 av[2], bv;
    int b_n = tid >> 2, b_q = tid & 3;

    auto gload = [&](int c) {
        const __half* A = (c >= 8) ? A2 : A1;
        const __half* B = (c >= 8) ? W2 : W1;
        int kk = (c & 7) * 32;
        #pragma unroll
        for (int i = 0; i < 2; i++) {
            int f = tid + i * 256, row = f >> 2, q = f & 3;
            int grow = bm + row;
            av[i] = (grow < M) ? __ldg((const uint4*)(A + (size_t)grow * DF + kk) + q)
                               : make_uint4(0u, 0u, 0u, 0u);
        }
        bv = __ldg((const uint4*)(B + (size_t)(bn + b_n) * DF + kk) + b_q);
    };

    auto sstore = [&](int buf) {
        char* st = smem + buf * S_BUF;
        #pragma unroll
        for (int i = 0; i < 2; i++) {
            int f = tid + i * 256, row = f >> 2, q = f & 3;
            *(uint4*)(st + S_A + row * 80 + q * 16) = av[i];
        }
        *(uint4*)(st + S_B + b_n * 80 + b_q * 16) = bv;
    };

    gload(0);
    sstore(0);
    __syncthreads();

    for (int c = 0; c < nc; c++) {
        int buf = c & 1;
        if (c + 1 < nc) gload(c + 1);

        uint32_t base = sb + buf * S_BUF;
        int a_row = wm * 32 + (lane & 15);
        int a_col = (lane >> 4) << 3;
        int b_row0 = wn * 32 + (lane & 7) + ((lane >> 4) << 3);
        int b_col = ((lane >> 3) & 1) << 3;

        #pragma unroll
        for (int ks = 0; ks < 2; ks++) {
            int kh = ks * 16;
            uint32_t ah[8], bh[8];
            #pragma unroll
            for (int mt = 0; mt < 2; mt++) {
                uint32_t ad = base + S_A + (a_row + mt * 16) * 80 + (kh + a_col) * 2;
                ldsm_x4(ah + mt * 4, ad);
            }
            #pragma unroll
            for (int h = 0; h < 2; h++) {
                uint32_t bd = base + S_B + (b_row0 + h * 16) * 80 + (kh + b_col) * 2;
                ldsm_x4(bh + h * 4, bd);
            }
            #pragma unroll
            for (int mt = 0; mt < 2; mt++)
                #pragma unroll
                for (int nt = 0; nt < 4; nt++)
                    mma16816(acc[mt][nt], ah + mt * 4, bh[nt * 2], bh[nt * 2 + 1]);
        }
        if (c + 1 < nc) sstore((c + 1) & 1);
        __syncthreads();
    }

    // ---- epilogue: bias + relu; write fp16 ----
    int g = lane >> 2, tg = lane & 3;
    #pragma unroll
    for (int mt = 0; mt < 2; mt++) {
        int r0 = bm + wm * 32 + mt * 16 + g;
        #pragma unroll
        for (int nt = 0; nt < 4; nt++) {
            int col = bn + wn * 32 + nt * 8 + tg * 2;
            float bx = __ldg(bias + col), by = __ldg(bias + col + 1);
            float2 v0, v1;
            v0.x = acc[mt][nt][0] + bx; v0.y = acc[mt][nt][1] + by;
            v1.x = acc[mt][nt][2] + bx; v1.y = acc[mt][nt][3] + by;
            if (relu) {
                v0.x = fmaxf(v0.x, 0.f); v0.y = fmaxf(v0.y, 0.f);
                v1.x = fmaxf(v1.x, 0.f); v1.y = fmaxf(v1.y, 0.f);
            }
            if (r0 < M)
                *(uint32_t*)(Ch + (size_t)r0 * DF + col) = pack_f16(v0.x, v0.y);
            if (r0 + 8 < M)
                *(uint32_t*)(Ch + (size_t)(r0 + 8) * DF + col) = pack_f16(v1.x, v1.y);
        }
    }
}

// ---------------- decoder: logits (8) + softmax, warp per node (fp16 input) -----
__global__ void __launch_bounds__(128) k_decoder(
    const __half* __restrict__ H, const float* __restrict__ Wm2,
    const float* __restrict__ bm2, float* __restrict__ out)
{
    __shared__ float sW[8 * 256];
    int tid = threadIdx.x;
    #pragma unroll
    for (int i = 0; i < 16; i++) sW[tid + i * 128] = Wm2[tid + i * 128];
    __syncthreads();

    int lane = tid & 31, w = tid >> 5;
    int node = blockIdx.x * 4 + w;
    if (node >= N_NODES) return;

    float acc[8] = {0.f, 0.f, 0.f, 0.f, 0.f, 0.f, 0.f, 0.f};
    #pragma unroll
    for (int j = 0; j < 4; j++) {
        __half2 h2v = *(const __half2*)(H + (size_t)node * DF + j * 64 + lane * 2);
        float2 v = __half22float2(h2v);
        #pragma unroll
        for (int o = 0; o < 8; o++) {
            acc[o] = fmaf(v.x, sW[o * 256 + j * 64 + lane * 2], acc[o]);
            acc[o] = fmaf(v.y, sW[o * 256 + j * 64 + lane * 2 + 1], acc[o]);
        }
    }
    #pragma unroll
    for (int o = 0; o < 8; o++)
        #pragma unroll
        for (int off = 16; off >= 1; off >>= 1)
            acc[o] += __shfl_xor_sync(0xffffffffu, acc[o], off);

    if (lane < 8) {
        float logit = acc[lane] + bm2[lane];
        float m = logit;
        #pragma unroll
        for (int off = 4; off >= 1; off >>= 1)
            m = fmaxf(m, __shfl_xor_sync(0xffu, m, off));
        float ex = expf(logit - m);
        float ssum = ex;
        #pragma unroll
        for (int off = 4; off >= 1; off >>= 1)
            ssum += __shfl_xor_sync(0xffu, ssum, off);
        out[(size_t)node * 8 + lane] = ex / ssum;
    }
}

// ---------------- launch ----------------
extern "C" void kernel_launch(void* const* d_in, const int* in_sizes, int n_in,
                              void* d_out, int out_size) {
    const float* x    = (const float*)d_in[0];
    const void*  edge = d_in[1];
    const float* W1l = (const float*)d_in[2];
    const float* b1  = (const float*)d_in[3];
    const float* W1r = (const float*)d_in[4];
    const float* W2l = (const float*)d_in[5];
    const float* b2  = (const float*)d_in[6];
    const float* W2r = (const float*)d_in[7];
    const float* Wm1 = (const float*)d_in[8];
    const float* bm1 = (const float*)d_in[9];
    const float* Wm2 = (const float*)d_in[10];
    const float* bm2 = (const float*)d_in[11];
    float* out = (float*)d_out;

    __half *xb, *aggh, *h1b, *h2b, *hm, *w;
    cudaGetSymbolAddress((void**)&xb, g_xb);
    cudaGetSymbolAddress((void**)&aggh, g_aggh);
    cudaGetSymbolAddress((void**)&h1b, g_h1b);
    cudaGetSymbolAddress((void**)&h2b, g_h2b);
    cudaGetSymbolAddress((void**)&hm, g_hm);
    cudaGetSymbolAddress((void**)&w, g_w);

    cudaFuncSetAttribute(k_gemm_mma, cudaFuncAttributeMaxDynamicSharedMemorySize, SMEM_GEMM);

    // fused converts + CSR init + dtype detect + scan-flag reset
    k_convert<<<160 + XBLK + IBLK, 256>>>(W1l, W1r, W2l, W2r, Wm1, x, edge);

    // CSR build
    k_count<<<(N_EDGES / 2 + 255) / 256, 256>>>(edge);
    k_scan<<<49, 1024>>>();
    k_fill<<<(N_EDGES / 2 + 255) / 256, 256>>>(edge);

    int aggBlocks = (N_NODES * 32 + 255) / 256;
    dim3 gg((N_NODES + 127) / 128, 4);

    // layer 1
    k_aggregate<<<aggBlocks, 256>>>(xb, aggh);
    k_gemm_mma<<<gg, 256, SMEM_GEMM>>>(aggh, w + 0 * DF * DF, xb, w + 1 * DF * DF,
                                       b1, h1b, N_NODES, 1, 1);

    // layer 2
    k_aggregate<<<aggBlocks, 256>>>(h1b, aggh);
    k_gemm_mma<<<gg, 256, SMEM_GEMM>>>(aggh, w + 2 * DF * DF, h1b, w + 3 * DF * DF,
                                       b2, h2b, N_NODES, 1, 1);

    // MLP hidden (fp16 out)
    k_gemm_mma<<<gg, 256, SMEM_GEMM>>>(h2b, w + 4 * DF * DF, nullptr, w + 4 * DF * DF,
                                       bm1, hm, N_NODES, 0, 1);

    // decoder + softmax
    k_decoder<<<(N_NODES + 3) / 4, 128>>>(hm, Wm2, bm2, out);
}

// round 16
// speedup vs baseline: 1.5244x; 1.5244x over previous
#include <cuda_runtime.h>
#include <cuda_fp16.h>
#include <cstdint>

#define N_NODES 50000
#define N_EDGES 800000
#define DF 256

// ---------------- device scratch ----------------
__device__ int    g_is64;
__device__ int    g_deg[N_NODES];
__device__ int    g_cursor[N_NODES];
__device__ int    g_rowstart[N_NODES + 1];
__device__ int    g_blocksum[64];
__device__ int    g_nbr[N_EDGES];
__device__ __half g_xb[(size_t)N_NODES * DF];
__device__ __half g_aggh[(size_t)N_NODES * DF];
__device__ __half g_h1b[(size_t)N_NODES * DF];
__device__ __half g_h2b[(size_t)N_NODES * DF];
__device__ __half g_hm[(size_t)N_NODES * DF];
__device__ __half g_w[5][DF * DF];

__device__ __forceinline__ int edge_at(const void* edge, int idx) {
    if (g_is64) return (int)((const long long*)edge)[idx];
    return ((const int*)edge)[idx];
}

// ---------------- helpers ----------------
__device__ __forceinline__ uint32_t s2u(const void* p) {
    uint32_t a;
    asm("{ .reg .u64 t; cvta.to.shared.u64 t, %1; cvt.u32.u64 %0, t; }" : "=r"(a) : "l"(p));
    return a;
}
__device__ __forceinline__ uint32_t pack_f16(float a, float b) {
    __half2 h = __floats2half2_rn(a, b);
    return *reinterpret_cast<uint32_t*>(&h);
}

// ---- fused: weight fp16 convert + x fp16 convert + CSR init + dtype detect ----
#define XBLK ((N_NODES * DF / 8 + 255) / 256)
#define IBLK ((N_NODES + 255) / 256)
__global__ void k_convert(const float* __restrict__ w0, const float* __restrict__ w1,
                          const float* __restrict__ w2, const float* __restrict__ w3,
                          const float* __restrict__ w4, const float* __restrict__ x,
                          const void* edge) {
    int b = blockIdx.x;
    if (b >= 160 + XBLK) {
        int i = (b - 160 - XBLK) * blockDim.x + threadIdx.x;
        if (i < N_NODES) { g_deg[i] = 0; g_cursor[i] = 0; }
        if (i == 0) {
            const long long* e = (const long long*)edge;
            int ok = 1;
            for (int j = 0; j < 16; j++) {
                long long v = e[j];
                if (v < 0 || v >= (long long)N_NODES) ok = 0;
            }
            g_is64 = ok;
        }
        return;
    }
    const float* src;
    uint4* dst;
    int i;
    if (b < 160) {
        int m = b >> 5;
        i = (b & 31) * blockDim.x + threadIdx.x;
        src = (m == 0) ? w0 : (m == 1) ? w1 : (m == 2) ? w2 : (m == 3) ? w3 : w4;
        dst = (uint4*)g_w[m];
    } else {
        i = (b - 160) * blockDim.x + threadIdx.x;
        if (i >= N_NODES * DF / 8) return;
        src = x;
        dst = (uint4*)g_xb;
    }
    const float4* p = (const float4*)src + (size_t)i * 2;
    float4 v0 = __ldg(p), v1 = __ldg(p + 1);
    uint4 o;
    o.x = pack_f16(v0.x, v0.y); o.y = pack_f16(v0.z, v0.w);
    o.z = pack_f16(v1.x, v1.y); o.w = pack_f16(v1.z, v1.w);
    dst[i] = o;
}

// ---------------- CSR build ----------------
__global__ void k_count(const void* __restrict__ edge) {
    int e = blockIdx.x * blockDim.x + threadIdx.x;
    if (e >= N_EDGES) return;
    int dst = edge_at(edge, N_EDGES + e);
    atomicAdd(&g_deg[dst], 1);
}

__global__ void k_scanA() {
    __shared__ int ws[32];
    int b = blockIdx.x, t = threadIdx.x, lane = t & 31, w = t >> 5;
    int i = b * 1024 + t;
    int v = (i < N_NODES) ? g_deg[i] : 0;
    int sv = v;
    #pragma unroll
    for (int off = 1; off < 32; off <<= 1) {
        int x = __shfl_up_sync(0xffffffffu, sv, off);
        if (lane >= off) sv += x;
    }
    if (lane == 31) ws[w] = sv;
    __syncthreads();
    if (w == 0) {
        int s = ws[lane];
        #pragma unroll
        for (int off = 1; off < 32; off <<= 1) {
            int x = __shfl_up_sync(0xffffffffu, s, off);
            if (lane >= off) s += x;
        }
        ws[lane] = s;
    }
    __syncthreads();
    int tot = sv + ((w > 0) ? ws[w - 1] : 0);
    if (i < N_NODES) g_rowstart[i + 1] = tot;
    if (t == 1023) g_blocksum[b] = tot;
    if (b == 0 && t == 0) g_rowstart[0] = 0;
}

// merged scanB+scanC: each block locally prefixes the 49 block sums, applies offset
__global__ void k_scanBC() {
    __shared__ int soff;
    int b = blockIdx.x, t = threadIdx.x;
    if (t == 0) {
        int acc = 0;
        for (int j = 0; j < b; j++) acc += g_blocksum[j];
        soff = acc;
    }
    __syncthreads();
    int i = b * 1024 + t;
    if (i < N_NODES) g_rowstart[i + 1] += soff;
}

__global__ void k_fill(const void* __restrict__ edge) {
    int e = blockIdx.x * blockDim.x + threadIdx.x;
    if (e >= N_EDGES) return;
    int src = edge_at(edge, e);
    int dst = edge_at(edge, N_EDGES + e);
    int p = atomicAdd(&g_cursor[dst], 1);
    g_nbr[g_rowstart[dst] + p] = src;
}

// ---------------- mean aggregation: warp per node, fp16, 8-edge unroll ----------------
__global__ void k_aggregate(const __half* __restrict__ Xb, __half* __restrict__ Oh) {
    int gw = (blockIdx.x * blockDim.x + threadIdx.x) >> 5;
    int lane = threadIdx.x & 31;
    if (gw >= N_NODES) return;
    int s = g_rowstart[gw], e = g_rowstart[gw + 1];
    float acc[8] = {0.f, 0.f, 0.f, 0.f, 0.f, 0.f, 0.f, 0.f};
    int j = s;
    for (; j + 8 <= e; j += 8) {
        uint4 u[8];
        #pragma unroll
        for (int k = 0; k < 8; k++) {
            int sk = g_nbr[j + k];
            u[k] = __ldg((const uint4*)(Xb + (size_t)sk * DF) + lane);
        }
        #pragma unroll
        for (int k = 0; k < 8; k++) {
            const __half2* p = (const __half2*)&u[k];
            #pragma unroll
            for (int i = 0; i < 4; i++) {
                float2 a = __half22float2(p[i]);
                acc[2 * i]     += a.x;
                acc[2 * i + 1] += a.y;
            }
        }
    }
    for (; j + 2 <= e; j += 2) {
        int s0 = g_nbr[j], s1 = g_nbr[j + 1];
        uint4 u0 = __ldg((const uint4*)(Xb + (size_t)s0 * DF) + lane);
        uint4 u1 = __ldg((const uint4*)(Xb + (size_t)s1 * DF) + lane);
        const __half2* p0 = (const __half2*)&u0;
        const __half2* p1 = (const __half2*)&u1;
        #pragma unroll
        for (int i = 0; i < 4; i++) {
            float2 a = __half22float2(p0[i]);
            float2 b = __half22float2(p1[i]);
            acc[2 * i]     += a.x + b.x;
            acc[2 * i + 1] += a.y + b.y;
        }
    }
    if (j < e) {
        int s0 = g_nbr[j];
        uint4 u = __ldg((const uint4*)(Xb + (size_t)s0 * DF) + lane);
        const __half2* up = (const __half2*)&u;
        #pragma unroll
        for (int i = 0; i < 4; i++) {
            float2 a = __half22float2(up[i]);
            acc[2 * i]     += a.x;
            acc[2 * i + 1] += a.y;
        }
    }
    int cnt = e - s;
    float inv = 1.0f / (float)(cnt > 1 ? cnt : 1);
    uint4 o;
    o.x = pack_f16(acc[0] * inv, acc[1] * inv);
    o.y = pack_f16(acc[2] * inv, acc[3] * inv);
    o.z = pack_f16(acc[4] * inv, acc[5] * inv);
    o.w = pack_f16(acc[6] * inv, acc[7] * inv);
    ((uint4*)(Oh + (size_t)gw * DF))[lane] = o;
}

// ======================= pure fp16 mma.sync GEMM =======================
// C = relu?( A1 @ W1^T [+ A2 @ W2^T] + bias ). All operands fp16, fp32 acc.
// CTA 128(M) x 64(N), chunk K=32, double-buffered smem, 2 CTAs/SM.  [R6 structure]

#define S_A 0
#define S_B 10240
#define S_BUF 15360
#define SMEM_GEMM (2 * S_BUF)

__device__ __forceinline__ void ldsm_x4(uint32_t* r, uint32_t addr) {
    asm volatile("ldmatrix.sync.aligned.m8n8.x4.shared.b16 {%0,%1,%2,%3}, [%4];"
                 : "=r"(r[0]), "=r"(r[1]), "=r"(r[2]), "=r"(r[3]) : "r"(addr));
}
__device__ __forceinline__ void mma16816(float* d, const uint32_t* a, uint32_t b0, uint32_t b1) {
    asm volatile(
        "mma.sync.aligned.m16n8k16.row.col.f32.f16.f16.f32 "
        "{%0,%1,%2,%3}, {%4,%5,%6,%7}, {%8,%9}, {%0,%1,%2,%3};"
        : "+f"(d[0]), "+f"(d[1]), "+f"(d[2]), "+f"(d[3])
        : "r"(a[0]), "r"(a[1]), "r"(a[2]), "r"(a[3]), "r"(b0), "r"(b1));
}

__global__ void __launch_bounds__(256, 2) k_gemm_mma(
    const __half* __restrict__ A1, const __half* __restrict__ W1,
    const __half* __restrict__ A2, const __half* __restrict__ W2,
    const float* __restrict__ bias,
    __half* __restrict__ Ch,
    int M, int dual, int relu)
{
    extern __shared__ __align__(16) char smem[];
    uint32_t sb = s2u(smem);
    int tid = threadIdx.x, lane = tid & 31, wid = tid >> 5;
    int bm = blockIdx.x * 128, bn = blockIdx.y * 64;
    int wm = wid & 3, wn = wid >> 2;

    float acc[2][4][4];
    #pragma unroll
    for (int mt = 0; mt < 2; mt++)
        #pragma unroll
        for (int nt = 0; nt < 4; nt++)
            #pragma unroll
            for (int j = 0; j < 4; j++) acc[mt][nt][j] = 0.f;

    int nc = dual ? 16 : 8;
    uint4 av[2], bv;
    int b_n = tid >> 2, b_q = tid & 3;

    auto gload = [&](int c) {
        const __half* A = (c >= 8) ? A2 : A1;
        const __half* B = (c >= 8) ? W2 : W1;
        int kk = (c & 7) * 32;
        #pragma unroll
        for (int i = 0; i < 2; i++) {
            int f = tid + i * 256, row = f >> 2, q = f & 3;
            int grow = bm + row;
            av[i] = (grow < M) ? __ldg((const uint4*)(A + (size_t)grow * DF + kk) + q)
                               : make_uint4(0u, 0u, 0u, 0u);
        }
        bv = __ldg((const uint4*)(B + (size_t)(bn + b_n) * DF + kk) + b_q);
    };

    auto sstore = [&](int buf) {
        char* st = smem + buf * S_BUF;
        #pragma unroll
        for (int i = 0; i < 2; i++) {
            int f = tid + i * 256, row = f >> 2, q = f & 3;
            *(uint4*)(st + S_A + row * 80 + q * 16) = av[i];
        }
        *(uint4*)(st + S_B + b_n * 80 + b_q * 16) = bv;
    };

    gload(0);
    sstore(0);
    __syncthreads();

    for (int c = 0; c < nc; c++) {
        int buf = c & 1;
        if (c + 1 < nc) gload(c + 1);

        uint32_t base = sb + buf * S_BUF;
        int a_row = wm * 32 + (lane & 15);
        int a_col = (lane >> 4) << 3;
        int b_row0 = wn * 32 + (lane & 7) + ((lane >> 4) << 3);
        int b_col = ((lane >> 3) & 1) << 3;

        #pragma unroll
        for (int ks = 0; ks < 2; ks++) {
            int kh = ks * 16;
            uint32_t ah[8], bh[8];
            #pragma unroll
            for (int mt = 0; mt < 2; mt++) {
                uint32_t ad = base + S_A + (a_row + mt * 16) * 80 + (kh + a_col) * 2;
                ldsm_x4(ah + mt * 4, ad);
            }
            #pragma unroll
            for (int h = 0; h < 2; h++) {
                uint32_t bd = base + S_B + (b_row0 + h * 16) * 80 + (kh + b_col) * 2;
                ldsm_x4(bh + h * 4, bd);
            }
            #pragma unroll
            for (int mt = 0; mt < 2; mt++)
                #pragma unroll
                for (int nt = 0; nt < 4; nt++)
                    mma16816(acc[mt][nt], ah + mt * 4, bh[nt * 2], bh[nt * 2 + 1]);
        }
        if (c + 1 < nc) sstore((c + 1) & 1);
        __syncthreads();
    }

    // ---- epilogue: bias + relu; write fp16 ----
    int g = lane >> 2, tg = lane & 3;
    #pragma unroll
    for (int mt = 0; mt < 2; mt++) {
        int r0 = bm + wm * 32 + mt * 16 + g;
        #pragma unroll
        for (int nt = 0; nt < 4; nt++) {
            int col = bn + wn * 32 + nt * 8 + tg * 2;
            float bx = __ldg(bias + col), by = __ldg(bias + col + 1);
            float2 v0, v1;
            v0.x = acc[mt][nt][0] + bx; v0.y = acc[mt][nt][1] + by;
            v1.x = acc[mt][nt][2] + bx; v1.y = acc[mt][nt][3] + by;
            if (relu) {
                v0.x = fmaxf(v0.x, 0.f); v0.y = fmaxf(v0.y, 0.f);
                v1.x = fmaxf(v1.x, 0.f); v1.y = fmaxf(v1.y, 0.f);
            }
            if (r0 < M)
                *(uint32_t*)(Ch + (size_t)r0 * DF + col) = pack_f16(v0.x, v0.y);
            if (r0 + 8 < M)
                *(uint32_t*)(Ch + (size_t)(r0 + 8) * DF + col) = pack_f16(v1.x, v1.y);
        }
    }
}

// ---------------- decoder: logits (8) + softmax, 8 nodes per 256-thread block ----
__global__ void __launch_bounds__(256) k_decoder(
    const __half* __restrict__ H, const float* __restrict__ Wm2,
    const float* __restrict__ bm2, float* __restrict__ out)
{
    __shared__ float sW[8 * 256];
    int tid = threadIdx.x;
    #pragma unroll
    for (int i = 0; i < 8; i++) sW[tid + i * 256] = Wm2[tid + i * 256];
    __syncthreads();

    int lane = tid & 31, w = tid >> 5;
    int node = blockIdx.x * 8 + w;
    if (node >= N_NODES) return;

    float acc[8] = {0.f, 0.f, 0.f, 0.f, 0.f, 0.f, 0.f, 0.f};
    #pragma unroll
    for (int j = 0; j < 4; j++) {
        __half2 h2v = *(const __half2*)(H + (size_t)node * DF + j * 64 + lane * 2);
        float2 v = __half22float2(h2v);
        #pragma unroll
        for (int o = 0; o < 8; o++) {
            acc[o] = fmaf(v.x, sW[o * 256 + j * 64 + lane * 2], acc[o]);
            acc[o] = fmaf(v.y, sW[o * 256 + j * 64 + lane * 2 + 1], acc[o]);
        }
    }
    #pragma unroll
    for (int o = 0; o < 8; o++)
        #pragma unroll
        for (int off = 16; off >= 1; off >>= 1)
            acc[o] += __shfl_xor_sync(0xffffffffu, acc[o], off);

    if (lane < 8) {
        float logit = acc[lane] + bm2[lane];
        float m = logit;
        #pragma unroll
        for (int off = 4; off >= 1; off >>= 1)
            m = fmaxf(m, __shfl_xor_sync(0xffu, m, off));
        float ex = expf(logit - m);
        float ssum = ex;
        #pragma unroll
        for (int off = 4; off >= 1; off >>= 1)
            ssum += __shfl_xor_sync(0xffu, ssum, off);
        out[(size_t)node * 8 + lane] = ex / ssum;
    }
}

// ---------------- launch ----------------
extern "C" void kernel_launch(void* const* d_in, const int* in_sizes, int n_in,
                              void* d_out, int out_size) {
    const float* x    = (const float*)d_in[0];
    const void*  edge = d_in[1];
    const float* W1l = (const float*)d_in[2];
    const float* b1  = (const float*)d_in[3];
    const float* W1r = (const float*)d_in[4];
    const float* W2l = (const float*)d_in[5];
    const float* b2  = (const float*)d_in[6];
    const float* W2r = (const float*)d_in[7];
    const float* Wm1 = (const float*)d_in[8];
    const float* bm1 = (const float*)d_in[9];
    const float* Wm2 = (const float*)d_in[10];
    const float* bm2 = (const float*)d_in[11];
    float* out = (float*)d_out;

    __half *xb, *aggh, *h1b, *h2b, *hm, *w;
    cudaGetSymbolAddress((void**)&xb, g_xb);
    cudaGetSymbolAddress((void**)&aggh, g_aggh);
    cudaGetSymbolAddress((void**)&h1b, g_h1b);
    cudaGetSymbolAddress((void**)&h2b, g_h2b);
    cudaGetSymbolAddress((void**)&hm, g_hm);
    cudaGetSymbolAddress((void**)&w, g_w);

    cudaFuncSetAttribute(k_gemm_mma, cudaFuncAttributeMaxDynamicSharedMemorySize, SMEM_GEMM);

    // fused converts + CSR init + dtype detect
    k_convert<<<160 + XBLK + IBLK, 256>>>(W1l, W1r, W2l, W2r, Wm1, x, edge);

    // CSR build (R14-proven)
    k_count<<<(N_EDGES + 255) / 256, 256>>>(edge);
    k_scanA<<<49, 1024>>>();
    k_scanBC<<<49, 1024>>>();
    k_fill<<<(N_EDGES + 255) / 256, 256>>>(edge);

    int aggBlocks = (N_NODES * 32 + 255) / 256;
    dim3 gg((N_NODES + 127) / 128, 4);

    // layer 1
    k_aggregate<<<aggBlocks, 256>>>(xb, aggh);
    k_gemm_mma<<<gg, 256, SMEM_GEMM>>>(aggh, w + 0 * DF * DF, xb, w + 1 * DF * DF,
                                       b1, h1b, N_NODES, 1, 1);

    // layer 2
    k_aggregate<<<aggBlocks, 256>>>(h1b, aggh);
    k_gemm_mma<<<gg, 256, SMEM_GEMM>>>(aggh, w + 2 * DF * DF, h1b, w + 3 * DF * DF,
                                       b2, h2b, N_NODES, 1, 1);

    // MLP hidden (fp16 out)
    k_gemm_mma<<<gg, 256, SMEM_GEMM>>>(h2b, w + 4 * DF * DF, nullptr, w + 4 * DF * DF,
                                       bm1, hm, N_NODES, 0, 1);

    // decoder + softmax
    k_decoder<<<(N_NODES + 7) / 8, 256>>>(hm, Wm2, bm2, out);
}

// round 17
// speedup vs baseline: 1.5291x; 1.0031x over previous
#include <cuda_runtime.h>
#include <cuda_fp16.h>
#include <cstdint>

#define N_NODES 50000
#define N_EDGES 800000
#define DF 256

// ---------------- device scratch ----------------
__device__ int    g_is64;
__device__ int    g_deg[N_NODES];
__device__ int    g_cursor[N_NODES];
__device__ int    g_rowstart[N_NODES + 1];
__device__ int    g_blocksum[64];
__device__ int    g_nbr[N_EDGES];
__device__ __half g_xb[(size_t)N_NODES * DF];
__device__ __half g_aggh[(size_t)N_NODES * DF];
__device__ __half g_h1b[(size_t)N_NODES * DF];
__device__ __half g_h2b[(size_t)N_NODES * DF];
__device__ __half g_hm[(size_t)N_NODES * DF];
__device__ __half g_w[5][DF * DF];

__device__ __forceinline__ int edge_at(const void* edge, int idx) {
    if (g_is64) return (int)((const long long*)edge)[idx];
    return ((const int*)edge)[idx];
}

// ---------------- helpers ----------------
__device__ __forceinline__ uint32_t s2u(const void* p) {
    uint32_t a;
    asm("{ .reg .u64 t; cvta.to.shared.u64 t, %1; cvt.u32.u64 %0, t; }" : "=r"(a) : "l"(p));
    return a;
}
__device__ __forceinline__ uint32_t pack_f16(float a, float b) {
    __half2 h = __floats2half2_rn(a, b);
    return *reinterpret_cast<uint32_t*>(&h);
}

// ---- fused: weight fp16 convert + x fp16 convert + CSR init + dtype detect ----
#define XBLK ((N_NODES * DF / 8 + 255) / 256)
#define IBLK ((N_NODES + 255) / 256)
__global__ void k_convert(const float* __restrict__ w0, const float* __restrict__ w1,
                          const float* __restrict__ w2, const float* __restrict__ w3,
                          const float* __restrict__ w4, const float* __restrict__ x,
                          const void* edge) {
    int b = blockIdx.x;
    if (b >= 160 + XBLK) {
        int i = (b - 160 - XBLK) * blockDim.x + threadIdx.x;
        if (i < N_NODES) g_deg[i] = 0;
        if (i == 0) {
            const long long* e = (const long long*)edge;
            int ok = 1;
            for (int j = 0; j < 16; j++) {
                long long v = e[j];
                if (v < 0 || v >= (long long)N_NODES) ok = 0;
            }
            g_is64 = ok;
        }
        return;
    }
    const float* src;
    uint4* dst;
    int i;
    if (b < 160) {
        int m = b >> 5;
        i = (b & 31) * blockDim.x + threadIdx.x;
        src = (m == 0) ? w0 : (m == 1) ? w1 : (m == 2) ? w2 : (m == 3) ? w3 : w4;
        dst = (uint4*)g_w[m];
    } else {
        i = (b - 160) * blockDim.x + threadIdx.x;
        if (i >= N_NODES * DF / 8) return;
        src = x;
        dst = (uint4*)g_xb;
    }
    const float4* p = (const float4*)src + (size_t)i * 2;
    float4 v0 = __ldg(p), v1 = __ldg(p + 1);
    uint4 o;
    o.x = pack_f16(v0.x, v0.y); o.y = pack_f16(v0.z, v0.w);
    o.z = pack_f16(v1.x, v1.y); o.w = pack_f16(v1.z, v1.w);
    dst[i] = o;
}

// ---------------- CSR build ----------------
__global__ void k_count(const void* __restrict__ edge) {
    int e = blockIdx.x * blockDim.x + threadIdx.x;
    if (e >= N_EDGES) return;
    int dst = edge_at(edge, N_EDGES + e);
    atomicAdd(&g_deg[dst], 1);
}

__global__ void k_scanA() {
    __shared__ int ws[32];
    int b = blockIdx.x, t = threadIdx.x, lane = t & 31, w = t >> 5;
    int i = b * 1024 + t;
    int v = (i < N_NODES) ? g_deg[i] : 0;
    int sv = v;
    #pragma unroll
    for (int off = 1; off < 32; off <<= 1) {
        int x = __shfl_up_sync(0xffffffffu, sv, off);
        if (lane >= off) sv += x;
    }
    if (lane == 31) ws[w] = sv;
    __syncthreads();
    if (w == 0) {
        int s = ws[lane];
        #pragma unroll
        for (int off = 1; off < 32; off <<= 1) {
            int x = __shfl_up_sync(0xffffffffu, s, off);
            if (lane >= off) s += x;
        }
        ws[lane] = s;
    }
    __syncthreads();
    int tot = sv + ((w > 0) ? ws[w - 1] : 0);
    if (i < N_NODES) g_rowstart[i + 1] = tot;
    if (t == 1023) g_blocksum[b] = tot;
    if (b == 0 && t == 0) g_rowstart[0] = 0;
}

// merged scanB+scanC + cursor seeding: cursor[i] = final rowstart[i]
__global__ void k_scanBC() {
    __shared__ int soff;
    int b = blockIdx.x, t = threadIdx.x;
    if (t == 0) {
        int acc = 0;
        for (int j = 0; j < b; j++) acc += g_blocksum[j];
        soff = acc;
    }
    __syncthreads();
    int i = b * 1024 + t;
    if (i < N_NODES) {
        int v = g_rowstart[i + 1] + soff;
        g_rowstart[i + 1] = v;
        if (i + 1 < N_NODES) g_cursor[i + 1] = v;
    }
    if (b == 0 && t == 0) g_cursor[0] = 0;
}

// fill with absolute cursor: no dependent rowstart read
__global__ void k_fill(const void* __restrict__ edge) {
    int e = blockIdx.x * blockDim.x + threadIdx.x;
    if (e >= N_EDGES) return;
    int src = edge_at(edge, e);
    int dst = edge_at(edge, N_EDGES + e);
    int p = atomicAdd(&g_cursor[dst], 1);
    g_nbr[p] = src;
}

// ---------------- mean aggregation: warp per node, fp16, 8-edge unroll ----------------
__global__ void k_aggregate(const __half* __restrict__ Xb, __half* __restrict__ Oh) {
    int gw = (blockIdx.x * blockDim.x + threadIdx.x) >> 5;
    int lane = threadIdx.x & 31;
    if (gw >= N_NODES) return;
    int s = g_rowstart[gw], e = g_rowstart[gw + 1];
    float acc[8] = {0.f, 0.f, 0.f, 0.f, 0.f, 0.f, 0.f, 0.f};
    int j = s;
    for (; j + 8 <= e; j += 8) {
        uint4 u[8];
        #pragma unroll
        for (int k = 0; k < 8; k++) {
            int sk = g_nbr[j + k];
            u[k] = __ldg((const uint4*)(Xb + (size_t)sk * DF) + lane);
        }
        #pragma unroll
        for (int k = 0; k < 8; k++) {
            const __half2* p = (const __half2*)&u[k];
            #pragma unroll
            for (int i = 0; i < 4; i++) {
                float2 a = __half22float2(p[i]);
                acc[2 * i]     += a.x;
                acc[2 * i + 1] += a.y;
            }
        }
    }
    for (; j + 2 <= e; j += 2) {
        int s0 = g_nbr[j], s1 = g_nbr[j + 1];
        uint4 u0 = __ldg((const uint4*)(Xb + (size_t)s0 * DF) + lane);
        uint4 u1 = __ldg((const uint4*)(Xb + (size_t)s1 * DF) + lane);
        const __half2* p0 = (const __half2*)&u0;
        const __half2* p1 = (const __half2*)&u1;
        #pragma unroll
        for (int i = 0; i < 4; i++) {
            float2 a = __half22float2(p0[i]);
            float2 b = __half22float2(p1[i]);
            acc[2 * i]     += a.x + b.x;
            acc[2 * i + 1] += a.y + b.y;
        }
    }
    if (j < e) {
        int s0 = g_nbr[j];
        uint4 u = __ldg((const uint4*)(Xb + (size_t)s0 * DF) + lane);
        const __half2* up = (const __half2*)&u;
        #pragma unroll
        for (int i = 0; i < 4; i++) {
            float2 a = __half22float2(up[i]);
            acc[2 * i]     += a.x;
            acc[2 * i + 1] += a.y;
        }
    }
    int cnt = e - s;
    float inv = 1.0f / (float)(cnt > 1 ? cnt : 1);
    uint4 o;
    o.x = pack_f16(acc[0] * inv, acc[1] * inv);
    o.y = pack_f16(acc[2] * inv, acc[3] * inv);
    o.z = pack_f16(acc[4] * inv, acc[5] * inv);
    o.w = pack_f16(acc[6] * inv, acc[7] * inv);
    ((uint4*)(Oh + (size_t)gw * DF))[lane] = o;
}

// ======================= pure fp16 mma.sync GEMM =======================
// C = relu?( A1 @ W1^T [+ A2 @ W2^T] + bias ). All operands fp16, fp32 acc.
// CTA 128(M) x 64(N), chunk K=32, double-buffered smem, 2 CTAs/SM.

#define S_A 0
#define S_B 10240
#define S_BUF 15360
#define SMEM_GEMM (2 * S_BUF)

__device__ __forceinline__ void ldsm_x4(uint32_t* r, uint32_t addr) {
    asm volatile("ldmatrix.sync.aligned.m8n8.x4.shared.b16 {%0,%1,%2,%3}, [%4];"
                 : "=r"(r[0]), "=r"(r[1]), "=r"(r[2]), "=r"(r[3]) : "r"(addr));
}
__device__ __forceinline__ void mma16816(float* d, const uint32_t* a, uint32_t b0, uint32_t b1) {
    asm volatile(
        "mma.sync.aligned.m16n8k16.row.col.f32.f16.f16.f32 "
        "{%0,%1,%2,%3}, {%4,%5,%6,%7}, {%8,%9}, {%0,%1,%2,%3};"
        : "+f"(d[0]), "+f"(d[1]), "+f"(d[2]), "+f"(d[3])
        : "r"(a[0]), "r"(a[1]), "r"(a[2]), "r"(a[3]), "r"(b0), "r"(b1));
}

__global__ void __launch_bounds__(256, 2) k_gemm_mma(
    const __half* __restrict__ A1, const __half* __restrict__ W1,
    const __half* __restrict__ A2, const __half* __restrict__ W2,
    const float* __restrict__ bias,
    __half* __restrict__ Ch,
    int M, int dual, int relu)
{
    extern __shared__ __align__(16) char smem[];
    uint32_t sb = s2u(smem);
    int tid = threadIdx.x, lane = tid & 31, wid = tid >> 5;
    int bm = blockIdx.x * 128, bn = blockIdx.y * 64;
    int wm = wid & 3, wn = wid >> 2;

    float acc[2][4][4];
    #pragma unroll
    for (int mt = 0; mt < 2; mt++)
        #pragma unroll
        for (int nt = 0; nt < 4; nt++)
            #pragma unroll
            for (int j = 0; j < 4; j++) acc[mt][nt][j] = 0.f;

    int nc = dual ? 16 : 8;
    uint4 av[2], bv;
    int b_n = tid >> 2, b_q = tid & 3;

    auto gload = [&](int c) {
        const __half* A = (c >= 8) ? A2 : A1;
        const __half* B = (c >= 8) ? W2 : W1;
        int kk = (c & 7) * 32;
        #pragma unroll
        for (int i = 0; i < 2; i++) {
            int f = tid + i * 256, row = f >> 2, q = f & 3;
            int grow = bm + row;
            av[i] = (grow < M) ? __ldg((const uint4*)(A + (size_t)grow * DF + kk) + q)
                               : make_uint4(0u, 0u, 0u, 0u);
        }
        bv = __ldg((const uint4*)(B + (size_t)(bn + b_n) * DF + kk) + b_q);
    };

    auto sstore = [&](int buf) {
        char* st = smem + buf * S_BUF;
        #pragma unroll
        for (int i = 0; i < 2; i++) {
            int f = tid + i * 256, row = f >> 2, q = f & 3;
            *(uint4*)(st + S_A + row * 80 + q * 16) = av[i];
        }
        *(uint4*)(st + S_B + b_n * 80 + b_q * 16) = bv;
    };

    gload(0);
    sstore(0);
    __syncthreads();

    for (int c = 0; c < nc; c++) {
        int buf = c & 1;
        if (c + 1 < nc) gload(c + 1);

        uint32_t base = sb + buf * S_BUF;
        int a_row = wm * 32 + (lane & 15);
        int a_col = (lane >> 4) << 3;
        int b_row0 = wn * 32 + (lane & 7) + ((lane >> 4) << 3);
        int b_col = ((lane >> 3) & 1) << 3;

        #pragma unroll
        for (int ks = 0; ks < 2; ks++) {
            int kh = ks * 16;
            uint32_t ah[8], bh[8];
            #pragma unroll
            for (int mt = 0; mt < 2; mt++) {
                uint32_t ad = base + S_A + (a_row + mt * 16) * 80 + (kh + a_col) * 2;
                ldsm_x4(ah + mt * 4, ad);
            }
            #pragma unroll
            for (int h = 0; h < 2; h++) {
                uint32_t bd = base + S_B + (b_row0 + h * 16) * 80 + (kh + b_col) * 2;
                ldsm_x4(bh + h * 4, bd);
            }
            #pragma unroll
            for (int mt = 0; mt < 2; mt++)
                #pragma unroll
                for (int nt = 0; nt < 4; nt++)
                    mma16816(acc[mt][nt], ah + mt * 4, bh[nt * 2], bh[nt * 2 + 1]);
        }
        if (c + 1 < nc) sstore((c + 1) & 1);
        __syncthreads();
    }

    // ---- epilogue: bias + relu; write fp16 ----
    int g = lane >> 2, tg = lane & 3;
    #pragma unroll
    for (int mt = 0; mt < 2; mt++) {
        int r0 = bm + wm * 32 + mt * 16 + g;
        #pragma unroll
        for (int nt = 0; nt < 4; nt++) {
            int col = bn + wn * 32 + nt * 8 + tg * 2;
            float bx = __ldg(bias + col), by = __ldg(bias + col + 1);
            float2 v0, v1;
            v0.x = acc[mt][nt][0] + bx; v0.y = acc[mt][nt][1] + by;
            v1.x = acc[mt][nt][2] + bx; v1.y = acc[mt][nt][3] + by;
            if (relu) {
                v0.x = fmaxf(v0.x, 0.f); v0.y = fmaxf(v0.y, 0.f);
                v1.x = fmaxf(v1.x, 0.f); v1.y = fmaxf(v1.y, 0.f);
            }
            if (r0 < M)
                *(uint32_t*)(Ch + (size_t)r0 * DF + col) = pack_f16(v0.x, v0.y);
            if (r0 + 8 < M)
                *(uint32_t*)(Ch + (size_t)(r0 + 8) * DF + col) = pack_f16(v1.x, v1.y);
        }
    }
}

// ---------------- decoder: logits (8) + softmax, 8 nodes per 256-thread block ----
__global__ void __launch_bounds__(256) k_decoder(
    const __half* __restrict__ H, const float* __restrict__ Wm2,
    const float* __restrict__ bm2, float* __restrict__ out)
{
    __shared__ float sW[8 * 256];
    int tid = threadIdx.x;
    #pragma unroll
    for (int i = 0; i < 8; i++) sW[tid + i * 256] = Wm2[tid + i * 256];
    __syncthreads();

    int lane = tid & 31, w = tid >> 5;
    int node = blockIdx.x * 8 + w;
    if (node >= N_NODES) return;

    float acc[8] = {0.f, 0.f, 0.f, 0.f, 0.f, 0.f, 0.f, 0.f};
    #pragma unroll
    for (int j = 0; j < 4; j++) {
        __half2 h2v = *(const __half2*)(H + (size_t)node * DF + j * 64 + lane * 2);
        float2 v = __half22float2(h2v);
        #pragma unroll
        for (int o = 0; o < 8; o++) {
            acc[o] = fmaf(v.x, sW[o * 256 + j * 64 + lane * 2], acc[o]);
            acc[o] = fmaf(v.y, sW[o * 256 + j * 64 + lane * 2 + 1], acc[o]);
        }
    }
    #pragma unroll
    for (int o = 0; o < 8; o++)
        #pragma unroll
        for (int off = 16; off >= 1; off >>= 1)
            acc[o] += __shfl_xor_sync(0xffffffffu, acc[o], off);

    if (lane < 8) {
        float logit = acc[lane] + bm2[lane];
        float m = logit;
        #pragma unroll
        for (int off = 4; off >= 1; off >>= 1)
            m = fmaxf(m, __shfl_xor_sync(0xffu, m, off));
        float ex = expf(logit - m);
        float ssum = ex;
        #pragma unroll
        for (int off = 4; off >= 1; off >>= 1)
            ssum += __shfl_xor_sync(0xffu, ssum, off);
        out[(size_t)node * 8 + lane] = ex / ssum;
    }
}

// ---------------- launch ----------------
extern "C" void kernel_launch(void* const* d_in, const int* in_sizes, int n_in,
                              void* d_out, int out_size) {
    const float* x    = (const float*)d_in[0];
    const void*  edge = d_in[1];
    const float* W1l = (const float*)d_in[2];
    const float* b1  = (const float*)d_in[3];
    const float* W1r = (const float*)d_in[4];
    const float* W2l = (const float*)d_in[5];
    const float* b2  = (const float*)d_in[6];
    const float* W2r = (const float*)d_in[7];
    const float* Wm1 = (const float*)d_in[8];
    const float* bm1 = (const float*)d_in[9];
    const float* Wm2 = (const float*)d_in[10];
    const float* bm2 = (const float*)d_in[11];
    float* out = (float*)d_out;

    __half *xb, *aggh, *h1b, *h2b, *hm, *w;
    cudaGetSymbolAddress((void**)&xb, g_xb);
    cudaGetSymbolAddress((void**)&aggh, g_aggh);
    cudaGetSymbolAddress((void**)&h1b, g_h1b);
    cudaGetSymbolAddress((void**)&h2b, g_h2b);
    cudaGetSymbolAddress((void**)&hm, g_hm);
    cudaGetSymbolAddress((void**)&w, g_w);

    cudaFuncSetAttribute(k_gemm_mma, cudaFuncAttributeMaxDynamicSharedMemorySize, SMEM_GEMM);

    // fused converts + CSR deg-zero + dtype detect
    k_convert<<<160 + XBLK + IBLK, 256>>>(W1l, W1r, W2l, W2r, Wm1, x, edge);

    // CSR build (cursor seeded with absolute offsets in scanBC)
    k_count<<<(N_EDGES + 255) / 256, 256>>>(edge);
    k_scanA<<<49, 1024>>>();
    k_scanBC<<<49, 1024>>>();
    k_fill<<<(N_EDGES + 255) / 256, 256>>>(edge);

    int aggBlocks = (N_NODES * 32 + 255) / 256;
    dim3 gg((N_NODES + 127) / 128, 4);

    // layer 1
    k_aggregate<<<aggBlocks, 256>>>(xb, aggh);
    k_gemm_mma<<<gg, 256, SMEM_GEMM>>>(aggh, w + 0 * DF * DF, xb, w + 1 * DF * DF,
                                       b1, h1b, N_NODES, 1, 1);

    // layer 2
    k_aggregate<<<aggBlocks, 256>>>(h1b, aggh);
    k_gemm_mma<<<gg, 256, SMEM_GEMM>>>(aggh, w + 2 * DF * DF, h1b, w + 3 * DF * DF,
                                       b2, h2b, N_NODES, 1, 1);

    // MLP hidden (fp16 out)
    k_gemm_mma<<<gg, 256, SMEM_GEMM>>>(h2b, w + 4 * DF * DF, nullptr, w + 4 * DF * DF,
                                       bm1, hm, N_NODES, 0, 1);

    // decoder + softmax
    k_decoder<<<(N_NODES + 7) / 8, 256>>>(hm, Wm2, bm2, out);
}